// round 9
// baseline (speedup 1.0000x reference)
#include <cuda_runtime.h>
#include <cuda_fp16.h>
#include <stdint.h>

#define D_    64
#define NROW  16384
#define KCB   8192
#define BM    64
#define BN    128
#define NT    256
#define KT    (KCB / BN)     // 64
#define CAP   256
#define PI8   80             // int8 row pitch (bytes)
#define PH    136            // fp16 A row pitch (bytes, 17*8 -> conflict-free LDS.64)

__device__ float    g_xsq[NROW];
__device__ float    g_wsq[KCB];
__device__ float    g_xl1[NROW];
__device__ float    g_xamax[NROW];
__device__ int      g_wamax_bits;
__device__ int      g_wl1max_bits;
__device__ int      g_wsqmax_bits;
__device__ uint32_t g_xq8[NROW * 16];     // packed int8x4 per x row
__device__ uint2    g_xh[NROW * 16];      // fp16x4 per x row (step-major)
__device__ uint32_t g_wq8s[KT * 64 * 16]; // int8 strips: tile-local cols 0..63
__device__ uint2    g_whT[KT * 1024];     // fp16 strips transposed [tt][step][lcol]
__device__ float    g_c2s[NROW];          // -2*sx*sw
__device__ float    g_m2B[NROW];          // candidate margin
__device__ int      g_cnt[NROW];
__device__ int      g_cand[NROW * CAP];
__device__ float    g_rowloss[NROW];

// ---------------------------------------------------------------------------
__device__ __forceinline__ uint32_t smem_u32(const void* p) {
    uint32_t a;
    asm("{ .reg .u64 t; cvta.to.shared.u64 t, %1; cvt.u32.u64 %0, t; }" : "=r"(a) : "l"(p));
    return a;
}
__device__ __forceinline__ void cp16(uint32_t dst, const void* src) {
    asm volatile("cp.async.cg.shared.global [%0], [%1], 16;" :: "r"(dst), "l"(src));
}
__device__ __forceinline__ void cp8(uint32_t dst, const void* src) {
    asm volatile("cp.async.ca.shared.global [%0], [%1], 8;" :: "r"(dst), "l"(src));
}
__device__ __forceinline__ void cp_commit() { asm volatile("cp.async.commit_group;"); }
__device__ __forceinline__ void cp_wait1()  { asm volatile("cp.async.wait_group 1;"); }
__device__ __forceinline__ void cp_wait0()  { asm volatile("cp.async.wait_group 0;"); }

__device__ __forceinline__ int dp4a_(uint32_t a, uint32_t b, int c) {
    int d;
    asm("dp4a.s32.s32 %0, %1, %2, %3;" : "=r"(d) : "r"(a), "r"(b), "r"(c));
    return d;
}
__device__ __forceinline__ uint32_t pack4(float a, float b, float c, float d, float inv) {
    int q0 = __float2int_rn(a * inv) & 0xff;
    int q1 = __float2int_rn(b * inv) & 0xff;
    int q2 = __float2int_rn(c * inv) & 0xff;
    int q3 = __float2int_rn(d * inv) & 0xff;
    return (uint32_t)(q0 | (q1 << 8) | (q2 << 16) | (q3 << 24));
}
__device__ __forceinline__ __half2 h2fma(uint32_t a, uint32_t b, __half2 c) {
    return __hfma2(*reinterpret_cast<__half2*>(&a), *reinterpret_cast<__half2*>(&b), c);
}

// ---------------------------------------------------------------------------
// prep1: warp-per-row norms / absmax / L1 + global maxes for w
// ---------------------------------------------------------------------------
__global__ __launch_bounds__(256) void prep1_kernel(const float* __restrict__ x,
                                                    const float* __restrict__ w) {
    int gw = (blockIdx.x * 256 + threadIdx.x) >> 5;
    int lane = threadIdx.x & 31;
    if (gw >= NROW + KCB) return;
    const float* src = (gw < NROW) ? x : w;
    int row = (gw < NROW) ? gw : gw - NROW;

    float2 v = ((const float2*)(src + (size_t)row * D_))[lane];
    float s  = v.x * v.x + v.y * v.y;
    float l1 = fabsf(v.x) + fabsf(v.y);
    float am = fmaxf(fabsf(v.x), fabsf(v.y));
#pragma unroll
    for (int o = 16; o > 0; o >>= 1) {
        s  += __shfl_xor_sync(0xffffffffu, s, o);
        l1 += __shfl_xor_sync(0xffffffffu, l1, o);
        am  = fmaxf(am, __shfl_xor_sync(0xffffffffu, am, o));
    }
    if (lane == 0) {
        if (gw < NROW) {
            g_xsq[row] = s; g_xl1[row] = l1; g_xamax[row] = am; g_cnt[row] = 0;
        } else {
            g_wsq[row] = s;
            atomicMax(&g_wamax_bits,  __float_as_int(am));
            atomicMax(&g_wl1max_bits, __float_as_int(l1));
            atomicMax(&g_wsqmax_bits, __float_as_int(s));
        }
    }
}

// ---------------------------------------------------------------------------
// prep2: x -> int8 + fp16 + margins;  w -> int8 strip (cols<64) or fp16 strip
// ---------------------------------------------------------------------------
__global__ __launch_bounds__(256) void prep2_kernel(const float* __restrict__ x,
                                                    const float* __restrict__ w) {
    int row = blockIdx.x * 256 + threadIdx.x;
    if (row >= NROW + KCB) return;
    float wam = fmaxf(__int_as_float(g_wamax_bits), 1e-30f);
    float sw = wam * (1.f / 127.f);
    if (row < NROW) {
        float am = fmaxf(g_xamax[row], 1e-30f);
        float sx = am * (1.f / 127.f);
        float inv = 127.f / am;
        const float4* xr = (const float4*)(x + (size_t)row * D_);
#pragma unroll
        for (int q = 0; q < 16; q++) {
            float4 v = xr[q];
            g_xq8[row * 16 + q] = pack4(v.x, v.y, v.z, v.w, inv);
            __half2 h01 = __floats2half2_rn(v.x, v.y);
            __half2 h23 = __floats2half2_rn(v.z, v.w);
            g_xh[row * 16 + q] = make_uint2(*reinterpret_cast<uint32_t*>(&h01),
                                            *reinterpret_cast<uint32_t*>(&h23));
        }
        float l1w = __int_as_float(g_wl1max_bits);
        float xq  = g_xsq[row];
        float doterr_i8 = 0.5f * sw * g_xl1[row] + 0.5f * sx * l1w + 16.f * sx * sw;
        float wn2max = sqrtf(fmaxf(__int_as_float(g_wsqmax_bits), 0.f));
        float doterr_h = 0.03f * sqrtf(xq) * wn2max + 1e-4f;
        g_c2s[row] = -2.f * sx * sw;
        g_m2B[row] = 4.f * fmaxf(doterr_i8, doterr_h);
    } else {
        int r = row - NROW;
        int tt = r >> 7, pos = r & 127;
        const float4* wr = (const float4*)(w + (size_t)r * D_);
        if (pos < 64) {
            float inv = 127.f / wam;
#pragma unroll
            for (int q = 0; q < 16; q++) {
                float4 v = wr[q];
                g_wq8s[((size_t)tt * 64 + pos) * 16 + q] = pack4(v.x, v.y, v.z, v.w, inv);
            }
        } else {
            int lcol = pos - 64;
#pragma unroll
            for (int st = 0; st < 16; st++) {
                float4 v = wr[st];
                __half2 h01 = __floats2half2_rn(v.x, v.y);
                __half2 h23 = __floats2half2_rn(v.z, v.w);
                g_whT[(size_t)tt * 1024 + st * 64 + lcol] =
                    make_uint2(*reinterpret_cast<uint32_t*>(&h01),
                               *reinterpret_cast<uint32_t*>(&h23));
            }
        }
    }
}

// ---------------------------------------------------------------------------
// vq_filter: hybrid dp4a (cols 0-63) + HFMA2 (cols 64-127) candidate filter
// 64x128 tiles, 256 threads, TM=4, TN=4+4, 2 CTAs/SM
// ---------------------------------------------------------------------------
__global__ __launch_bounds__(NT, 2) void vq_filter() {
    __shared__ uint8_t xsA[BM * PI8];            // 5120
    __shared__ uint8_t xhA[BM * PH];             // 8704
    __shared__ uint8_t wi8[2][64 * PI8];         // 2 x 5120
    __shared__ uint8_t whT[2][16 * 64 * 8];      // 2 x 8192
    __shared__ float   wsqs[2][BN];              // 2 x 512

    const uint32_t sbA  = smem_u32(xsA);
    const uint32_t sbAh = smem_u32(xhA);
    const uint32_t sbI  = smem_u32(wi8);
    const uint32_t sbH  = smem_u32(whT);
    const uint32_t sbQ  = smem_u32(wsqs);

    const int t = threadIdx.x;
    const int tx = t & 15, ty = t >> 4;
    const int rowBase = blockIdx.x * BM;

    // A int8: 256 x 16B
    {
        int r = t >> 2, q = t & 3;
        cp16(sbA + r * PI8 + q * 16, g_xq8 + (size_t)(rowBase + r) * 16 + q * 4);
    }
    // A fp16: 1024 x 8B
#pragma unroll
    for (int i = 0; i < 4; i++) {
        int idx = t + i * NT;
        int r = idx >> 4, st = idx & 15;
        cp8(sbAh + r * PH + st * 8, g_xh + (size_t)(rowBase + r) * 16 + st);
    }

    auto issue = [&](int tt, int b) {
        // int8 strip: 256 x 16B
        {
            int r = t >> 2, q = t & 3;
            cp16(sbI + b * (64 * PI8) + r * PI8 + q * 16,
                 g_wq8s + ((size_t)tt * 64 + r) * 16 + q * 4);
        }
        // fp16 strip: 512 x 16B (linear)
#pragma unroll
        for (int i = 0; i < 2; i++) {
            int idx = t + i * NT;
            cp16(sbH + b * 8192 + idx * 16,
                 (const char*)g_whT + (size_t)tt * 8192 + idx * 16);
        }
        if (t < 32) cp16(sbQ + b * (BN * 4) + t * 16, g_wsq + tt * BN + t * 4);
    };

    issue(0, 0);
    cp_commit();

    float xqs[4], gmin[4], m2B[4], c2s[4];
    int rowid[4];
#pragma unroll
    for (int r = 0; r < 4; r++) {
        int row = rowBase + ty + 16 * r;
        rowid[r] = row;
        xqs[r] = g_xsq[row];
        m2B[r] = g_m2B[row];
        c2s[r] = g_c2s[row];
        gmin[r] = 3.4e38f;
    }

    const __half2 hz = __float2half2_rn(0.f);

    for (int tt = 0; tt < KT; tt++) {
        const int buf = tt & 1;
        if (tt + 1 < KT) { issue(tt + 1, buf ^ 1); cp_commit(); cp_wait1(); }
        else             { cp_wait0(); }
        __syncthreads();

        const uint8_t* wtI = wi8[buf];
        const uint8_t* wtH = whT[buf];

        int acc_i[4][4];
        __half2 acc_h[4][4];
#pragma unroll
        for (int r = 0; r < 4; r++)
#pragma unroll
            for (int c = 0; c < 4; c++) { acc_i[r][c] = 0; acc_h[r][c] = hz; }

        // fused loop: 8 outer steps; each = 1 int8 kq2-step + 2 fp16 steps
#pragma unroll
        for (int s8 = 0; s8 < 8; s8++) {
            uint2 a2[4], b2[4];
#pragma unroll
            for (int r = 0; r < 4; r++)
                a2[r] = *(const uint2*)(xsA + (ty + 16 * r) * PI8 + s8 * 8);
#pragma unroll
            for (int c = 0; c < 4; c++)
                b2[c] = *(const uint2*)(wtI + (tx + 16 * c) * PI8 + s8 * 8);

            uint2 ah0[4], bh0[4], ah1[4], bh1[4];
            const int st0 = 2 * s8, st1 = 2 * s8 + 1;
#pragma unroll
            for (int r = 0; r < 4; r++) {
                ah0[r] = *(const uint2*)(xhA + (ty + 16 * r) * PH + st0 * 8);
                ah1[r] = *(const uint2*)(xhA + (ty + 16 * r) * PH + st1 * 8);
            }
#pragma unroll
            for (int c = 0; c < 4; c++) {
                bh0[c] = *(const uint2*)(wtH + (st0 * 64 + tx + 16 * c) * 8);
                bh1[c] = *(const uint2*)(wtH + (st1 * 64 + tx + 16 * c) * 8);
            }

#pragma unroll
            for (int r = 0; r < 4; r++)
#pragma unroll
                for (int c = 0; c < 4; c++) {
                    acc_i[r][c] = dp4a_(a2[r].x, b2[c].x, acc_i[r][c]);
                    acc_h[r][c] = h2fma(ah0[r].x, bh0[c].x, acc_h[r][c]);
                    acc_i[r][c] = dp4a_(a2[r].y, b2[c].y, acc_i[r][c]);
                    acc_h[r][c] = h2fma(ah0[r].y, bh0[c].y, acc_h[r][c]);
                    acc_h[r][c] = h2fma(ah1[r].x, bh1[c].x, acc_h[r][c]);
                    acc_h[r][c] = h2fma(ah1[r].y, bh1[c].y, acc_h[r][c]);
                }
        }

        // epilogue
        const float* wqS = wsqs[buf];
        const int gBase = tt * BN;
#pragma unroll
        for (int c = 0; c < 4; c++) {
            int colI = tx + 16 * c;
            float wqI = wqS[colI];
            float wqH = wqS[64 + colI];
#pragma unroll
            for (int r = 0; r < 4; r++) {
                float dI = fmaf(c2s[r], (float)acc_i[r][c], xqs[r] + wqI);
                float2 fh = __half22float2(acc_h[r][c]);
                float dH = fmaf(-2.f, fh.x + fh.y, xqs[r] + wqH);
                float thr = gmin[r] + m2B[r];
                if (dI <= thr) {
                    int p = atomicAdd(&g_cnt[rowid[r]], 1);
                    if (p < CAP) g_cand[rowid[r] * CAP + p] = gBase + colI;
                }
                if (dH <= thr) {
                    int p = atomicAdd(&g_cnt[rowid[r]], 1);
                    if (p < CAP) g_cand[rowid[r] * CAP + p] = gBase + 64 + colI;
                }
                gmin[r] = fminf(gmin[r], fminf(dI, dH));
            }
        }
#pragma unroll
        for (int r = 0; r < 4; r++) {
            float v = gmin[r];
            v = fminf(v, __shfl_xor_sync(0xffffffffu, v, 1));
            v = fminf(v, __shfl_xor_sync(0xffffffffu, v, 2));
            v = fminf(v, __shfl_xor_sync(0xffffffffu, v, 4));
            v = fminf(v, __shfl_xor_sync(0xffffffffu, v, 8));
            gmin[r] = v;
        }
        __syncthreads();
    }
}

// ---------------------------------------------------------------------------
// rescore: exact fp32 argmin over candidates (warp per row), lowest-index ties
// out: [0]=loss, [1..N*D]=quantized, [1+N*D..]=indices (float)
// ---------------------------------------------------------------------------
__global__ __launch_bounds__(256) void rescore_kernel(const float* __restrict__ x,
                                                      const float* __restrict__ w,
                                                      float* __restrict__ out) {
    int row = (blockIdx.x * 256 + threadIdx.x) >> 5;
    int lane = threadIdx.x & 31;
    if (row >= NROW) return;

    int cnt = g_cnt[row];
    if (cnt > CAP) cnt = CAP;
    const int* cl = g_cand + (size_t)row * CAP;
    float2 xv = ((const float2*)(x + (size_t)row * D_))[lane];

    int bc;
    if (cnt == 1) {
        bc = cl[0];
    } else {
        float xq = g_xsq[row];
        float bd = 3.4e38f;
        bc = 0x7fffffff;
        int i = 0;
        for (; i + 2 <= cnt; i += 2) {
            int c0 = cl[i], c1 = cl[i + 1];
            float2 w0 = ((const float2*)(w + (size_t)c0 * D_))[lane];
            float2 w1 = ((const float2*)(w + (size_t)c1 * D_))[lane];
            float p0 = xv.x * w0.x + xv.y * w0.y;
            float p1 = xv.x * w1.x + xv.y * w1.y;
#pragma unroll
            for (int o = 16; o > 0; o >>= 1) {
                p0 += __shfl_xor_sync(0xffffffffu, p0, o);
                p1 += __shfl_xor_sync(0xffffffffu, p1, o);
            }
            float d0 = xq + g_wsq[c0] - 2.f * p0;
            float d1 = xq + g_wsq[c1] - 2.f * p1;
            if (d0 < bd || (d0 == bd && c0 < bc)) { bd = d0; bc = c0; }
            if (d1 < bd || (d1 == bd && c1 < bc)) { bd = d1; bc = c1; }
        }
        if (i < cnt) {
            int c0 = cl[i];
            float2 w0 = ((const float2*)(w + (size_t)c0 * D_))[lane];
            float p0 = xv.x * w0.x + xv.y * w0.y;
#pragma unroll
            for (int o = 16; o > 0; o >>= 1) p0 += __shfl_xor_sync(0xffffffffu, p0, o);
            float d0 = xq + g_wsq[c0] - 2.f * p0;
            if (d0 < bd || (d0 == bd && c0 < bc)) { bd = d0; bc = c0; }
        }
    }

    float2 wv = ((const float2*)(w + (size_t)bc * D_))[lane];
    float* qo = out + 1 + (size_t)row * D_ + lane * 2;   // 4B-aligned: scalar stores
    qo[0] = wv.x;
    qo[1] = wv.y;
    if (lane == 0) out[1 + (size_t)NROW * D_ + row] = (float)bc;

    float dx = wv.x - xv.x, dy = wv.y - xv.y;
    float l = dx * dx + dy * dy;
#pragma unroll
    for (int o = 16; o > 0; o >>= 1) l += __shfl_xor_sync(0xffffffffu, l, o);
    if (lane == 0) g_rowloss[row] = l;
}

// ---------------------------------------------------------------------------
__global__ void finalize_kernel(float* __restrict__ out) {
    __shared__ float sm[256];
    float s = 0.f;
    for (int i = threadIdx.x; i < NROW; i += 256) s += g_rowloss[i];
    sm[threadIdx.x] = s;
    __syncthreads();
    for (int o = 128; o > 0; o >>= 1) {
        if (threadIdx.x < o) sm[threadIdx.x] += sm[threadIdx.x + o];
        __syncthreads();
    }
    if (threadIdx.x == 0) out[0] = 1.25f * sm[0] / (float)(NROW * D_);
}

// ---------------------------------------------------------------------------
extern "C" void kernel_launch(void* const* d_in, const int* in_sizes, int n_in,
                              void* d_out, int out_size) {
    const float* x = (const float*)d_in[0];
    const float* w = (const float*)d_in[1];
    float* out = (float*)d_out;

    prep1_kernel<<<(NROW + KCB) / 8, 256>>>(x, w);
    prep2_kernel<<<(NROW + KCB + 255) / 256, 256>>>(x, w);
    vq_filter<<<NROW / BM, NT>>>();
    rescore_kernel<<<NROW / 8, 256>>>(x, w, out);
    finalize_kernel<<<1, 256>>>(out);
}

// round 10
// speedup vs baseline: 1.0983x; 1.0983x over previous
#include <cuda_runtime.h>
#include <stdint.h>

#define D_    64
#define NROW  16384
#define KCB   8192
#define BM    64
#define BN    128
#define NT    256
#define KT    (KCB / BN)     // 64
#define CAP   256
#define PI8   80             // int8 row pitch in smem (64 data + 16 pad)

__device__ float    g_xsq[NROW];
__device__ float    g_wsq[KCB];
__device__ float    g_xl1[NROW];
__device__ float    g_xamax[NROW];
__device__ int      g_wamax_bits;
__device__ int      g_wl1max_bits;
__device__ uint32_t g_xq8[NROW * 16];   // packed int8x4
__device__ uint32_t g_wq8[KCB * 16];
__device__ int      g_cnt[NROW];
__device__ int      g_cand[NROW * CAP];
__device__ float    g_rowloss[NROW];

// ---------------------------------------------------------------------------
__device__ __forceinline__ uint32_t smem_u32(const void* p) {
    uint32_t a;
    asm("{ .reg .u64 t; cvta.to.shared.u64 t, %1; cvt.u32.u64 %0, t; }" : "=r"(a) : "l"(p));
    return a;
}
__device__ __forceinline__ void cp16(uint32_t dst, const void* src) {
    asm volatile("cp.async.cg.shared.global [%0], [%1], 16;" :: "r"(dst), "l"(src));
}
__device__ __forceinline__ void cp_commit() { asm volatile("cp.async.commit_group;"); }
__device__ __forceinline__ void cp_wait1()  { asm volatile("cp.async.wait_group 1;"); }
__device__ __forceinline__ void cp_wait0()  { asm volatile("cp.async.wait_group 0;"); }

__device__ __forceinline__ int dp4a_(uint32_t a, uint32_t b, int c) {
    int d;
    asm("dp4a.s32.s32 %0, %1, %2, %3;" : "=r"(d) : "r"(a), "r"(b), "r"(c));
    return d;
}
__device__ __forceinline__ uint32_t pack4(float a, float b, float c, float d, float inv) {
    int q0 = __float2int_rn(a * inv) & 0xff;
    int q1 = __float2int_rn(b * inv) & 0xff;
    int q2 = __float2int_rn(c * inv) & 0xff;
    int q3 = __float2int_rn(d * inv) & 0xff;
    return (uint32_t)(q0 | (q1 << 8) | (q2 << 16) | (q3 << 24));
}

// ---------------------------------------------------------------------------
// prepA: warp-per-row. x rows: stats + int8 quantize + cnt reset.
//        w rows: stats + global atomicMax accumulators (idempotent).
// ---------------------------------------------------------------------------
__global__ __launch_bounds__(256) void prepA_kernel(const float* __restrict__ x,
                                                    const float* __restrict__ w) {
    int gw = (blockIdx.x * 256 + threadIdx.x) >> 5;
    int lane = threadIdx.x & 31;
    if (gw >= NROW + KCB) return;
    const bool isX = (gw < NROW);
    const float* src = isX ? x : w;
    int row = isX ? gw : gw - NROW;

    float2 v = ((const float2*)(src + (size_t)row * D_))[lane];
    float s  = v.x * v.x + v.y * v.y;
    float l1 = fabsf(v.x) + fabsf(v.y);
    float am = fmaxf(fabsf(v.x), fabsf(v.y));
#pragma unroll
    for (int o = 16; o > 0; o >>= 1) {
        s  += __shfl_xor_sync(0xffffffffu, s, o);
        l1 += __shfl_xor_sync(0xffffffffu, l1, o);
        am  = fmaxf(am, __shfl_xor_sync(0xffffffffu, am, o));
    }
    if (isX) {
        float amc = fmaxf(am, 1e-30f);
        float inv = 127.f / amc;
        int q0 = __float2int_rn(v.x * inv) & 0xff;
        int q1 = __float2int_rn(v.y * inv) & 0xff;
        uint32_t v16 = (uint32_t)(q0 | (q1 << 8));
        uint32_t hi = __shfl_down_sync(0xffffffffu, v16, 1);
        if (!(lane & 1)) g_xq8[row * 16 + (lane >> 1)] = v16 | (hi << 16);
        if (lane == 0) {
            g_xsq[row] = s; g_xl1[row] = l1; g_xamax[row] = amc; g_cnt[row] = 0;
        }
    } else if (lane == 0) {
        g_wsq[row] = s;
        atomicMax(&g_wamax_bits,  __float_as_int(am));
        atomicMax(&g_wl1max_bits, __float_as_int(l1));
    }
}

// ---------------------------------------------------------------------------
// prepW2: quantize w to int8 with global scale
// ---------------------------------------------------------------------------
__global__ __launch_bounds__(256) void prepW2_kernel(const float* __restrict__ w) {
    int r = blockIdx.x * 256 + threadIdx.x;
    if (r >= KCB) return;
    float wam = fmaxf(__int_as_float(g_wamax_bits), 1e-30f);
    float inv = 127.f / wam;
    const float4* wr = (const float4*)(w + (size_t)r * D_);
#pragma unroll
    for (int q = 0; q < 16; q++) {
        float4 v = wr[q];
        g_wq8[r * 16 + q] = pack4(v.x, v.y, v.z, v.w, inv);
    }
}

// ---------------------------------------------------------------------------
// vq_filter: int8 dp4a distance GEMM + provable candidate filter
// 64x128 tiles, 256 threads, TM=4 x TN=8, LDS.64 operands, 2 CTAs/SM
// ---------------------------------------------------------------------------
__global__ __launch_bounds__(NT, 2) void vq_filter() {
    __shared__ uint8_t xsA[BM * PI8];            // 5120 B
    __shared__ uint8_t wsm[2][BN * PI8];         // 2 x 10240 B
    __shared__ float   wsqs[2][BN];              // 2 x 512 B

    const uint32_t sbA = smem_u32(xsA);
    const uint32_t sbW = smem_u32(wsm);
    const uint32_t sbQ = smem_u32(wsqs);

    const int t = threadIdx.x;
    const int tx = t & 15, ty = t >> 4;
    const int rowBase = blockIdx.x * BM;

    // A tile: 64 rows x 64B = 256 x 16B (one cp16 per thread)
    {
        int r = t >> 2, q = t & 3;
        cp16(sbA + r * PI8 + q * 16, g_xq8 + (size_t)(rowBase + r) * 16 + q * 4);
    }
    auto issue = [&](int tt, int b) {
#pragma unroll
        for (int i = 0; i < 2; i++) {
            int idx = t + i * NT;                // 512 x 16B
            int r = idx >> 2, q = idx & 3;
            cp16(sbW + b * (BN * PI8) + r * PI8 + q * 16,
                 g_wq8 + ((size_t)tt * BN + r) * 16 + q * 4);
        }
        if (t < 32) cp16(sbQ + b * (BN * 4) + t * 16, g_wsq + tt * BN + t * 4);
    };

    issue(0, 0);
    cp_commit();

    // per-thread row state (rows ty + 16*r): margins computed from globals
    const float wam = fmaxf(__int_as_float(g_wamax_bits), 1e-30f);
    const float sw  = wam * (1.f / 127.f);
    const float l1w = __int_as_float(g_wl1max_bits);

    float xqs[4], gmin[4], m2B[4], c2s[4];
#pragma unroll
    for (int r = 0; r < 4; r++) {
        int row = rowBase + ty + 16 * r;
        float xam = g_xamax[row];
        float sx  = xam * (1.f / 127.f);
        float doterr = 0.5f * sw * g_xl1[row] + 0.5f * sx * l1w + 16.f * sx * sw;
        xqs[r]  = g_xsq[row];
        m2B[r]  = 4.f * doterr;
        c2s[r]  = -2.f * sx * sw;
        gmin[r] = 3.4e38f;
    }

    for (int tt = 0; tt < KT; tt++) {
        const int buf = tt & 1;
        if (tt + 1 < KT) { issue(tt + 1, buf ^ 1); cp_commit(); cp_wait1(); }
        else             { cp_wait0(); }
        __syncthreads();

        const uint8_t* wt = wsm[buf];
        int acc[4][8];
#pragma unroll
        for (int r = 0; r < 4; r++)
#pragma unroll
            for (int c = 0; c < 8; c++) acc[r][c] = 0;

#pragma unroll
        for (int kq2 = 0; kq2 < 8; kq2++) {      // 8 bytes of k per step
            uint2 a2[4], b2[8];
#pragma unroll
            for (int r = 0; r < 4; r++)
                a2[r] = *(const uint2*)(xsA + (ty + 16 * r) * PI8 + kq2 * 8);
#pragma unroll
            for (int c = 0; c < 8; c++)
                b2[c] = *(const uint2*)(wt + (tx + 16 * c) * PI8 + kq2 * 8);
#pragma unroll
            for (int r = 0; r < 4; r++)
#pragma unroll
                for (int c = 0; c < 8; c++) {
                    acc[r][c] = dp4a_(a2[r].x, b2[c].x, acc[r][c]);
                    acc[r][c] = dp4a_(a2[r].y, b2[c].y, acc[r][c]);
                }
        }

        // epilogue: stale-threshold superset window (thr fixed per tile)
        float thr[4];
#pragma unroll
        for (int r = 0; r < 4; r++) thr[r] = gmin[r] + m2B[r];

        const float* wqS = wsqs[buf];
#pragma unroll
        for (int c = 0; c < 8; c++) {
            int col = tx + 16 * c;
            float wq = wqS[col];
            int gcol = tt * BN + col;
#pragma unroll
            for (int r = 0; r < 4; r++) {
                float d = fmaf(c2s[r], (float)acc[r][c], xqs[r] + wq);
                if (d <= thr[r]) {
                    int p = atomicAdd(&g_cnt[rowBase + ty + 16 * r], 1);
                    if (p < CAP) g_cand[(rowBase + ty + 16 * r) * CAP + p] = gcol;
                }
                gmin[r] = fminf(gmin[r], d);
            }
        }
        // cross-lane tighten only every 2nd tile (stale min only widens window)
        if (tt & 1) {
#pragma unroll
            for (int r = 0; r < 4; r++) {
                float v = gmin[r];
                v = fminf(v, __shfl_xor_sync(0xffffffffu, v, 1));
                v = fminf(v, __shfl_xor_sync(0xffffffffu, v, 2));
                v = fminf(v, __shfl_xor_sync(0xffffffffu, v, 4));
                v = fminf(v, __shfl_xor_sync(0xffffffffu, v, 8));
                gmin[r] = v;
            }
        }
        __syncthreads();
    }
}

// ---------------------------------------------------------------------------
// rescore: lane-per-candidate exact fp32 argmin (warp per row)
// out: [0]=loss, [1..N*D]=quantized, [1+N*D..]=indices (float)
// ---------------------------------------------------------------------------
__global__ __launch_bounds__(256) void rescore_kernel(const float* __restrict__ x,
                                                      const float* __restrict__ w,
                                                      float* __restrict__ out) {
    int row = (blockIdx.x * 256 + threadIdx.x) >> 5;
    int lane = threadIdx.x & 31;
    if (row >= NROW) return;

    int cnt = g_cnt[row];
    if (cnt > CAP) cnt = CAP;
    const int* cl = g_cand + (size_t)row * CAP;

    int bc;
    if (cnt == 1) {
        bc = cl[0];
    } else {
        const float4* xr = (const float4*)(x + (size_t)row * D_);
        float xq = g_xsq[row];
        float bd = 3.4e38f;
        bc = 0x7fffffff;
        for (int base = 0; base < cnt; base += 32) {
            int L = base + lane;
            float d = 3.4e38f;
            int col = 0x7fffffff;
            if (L < cnt) {
                col = cl[L];
                const float4* wr = (const float4*)(w + (size_t)col * D_);
                float s0 = 0.f, s1 = 0.f, s2 = 0.f, s3 = 0.f;
#pragma unroll
                for (int q = 0; q < 16; q += 4) {
                    float4 a0 = xr[q],     b0 = wr[q];
                    float4 a1 = xr[q + 1], b1 = wr[q + 1];
                    float4 a2 = xr[q + 2], b2 = wr[q + 2];
                    float4 a3 = xr[q + 3], b3 = wr[q + 3];
                    s0 += a0.x * b0.x + a0.y * b0.y + a0.z * b0.z + a0.w * b0.w;
                    s1 += a1.x * b1.x + a1.y * b1.y + a1.z * b1.z + a1.w * b1.w;
                    s2 += a2.x * b2.x + a2.y * b2.y + a2.z * b2.z + a2.w * b2.w;
                    s3 += a3.x * b3.x + a3.y * b3.y + a3.z * b3.z + a3.w * b3.w;
                }
                float dot = (s0 + s1) + (s2 + s3);
                d = xq + g_wsq[col] - 2.f * dot;
            }
            if (d < bd || (d == bd && col < bc)) { bd = d; bc = col; }
        }
        // warp argmin (lexicographic (d, col)) — deterministic min over set
#pragma unroll
        for (int o = 16; o > 0; o >>= 1) {
            float od = __shfl_xor_sync(0xffffffffu, bd, o);
            int   oc = __shfl_xor_sync(0xffffffffu, bc, o);
            if (od < bd || (od == bd && oc < bc)) { bd = od; bc = oc; }
        }
    }

    float2 xv = ((const float2*)(x + (size_t)row * D_))[lane];
    float2 wv = ((const float2*)(w + (size_t)bc * D_))[lane];
    float* qo = out + 1 + (size_t)row * D_ + lane * 2;   // 4B-aligned: scalar stores
    qo[0] = wv.x;
    qo[1] = wv.y;
    if (lane == 0) out[1 + (size_t)NROW * D_ + row] = (float)bc;

    float dx = wv.x - xv.x, dy = wv.y - xv.y;
    float l = dx * dx + dy * dy;
#pragma unroll
    for (int o = 16; o > 0; o >>= 1) l += __shfl_xor_sync(0xffffffffu, l, o);
    if (lane == 0) g_rowloss[row] = l;
}

// ---------------------------------------------------------------------------
__global__ void finalize_kernel(float* __restrict__ out) {
    __shared__ float sm[512];
    float s = 0.f;
    for (int i = threadIdx.x; i < NROW; i += 512) s += g_rowloss[i];
    sm[threadIdx.x] = s;
    __syncthreads();
    for (int o = 256; o > 0; o >>= 1) {
        if (threadIdx.x < o) sm[threadIdx.x] += sm[threadIdx.x + o];
        __syncthreads();
    }
    if (threadIdx.x == 0) out[0] = 1.25f * sm[0] / (float)(NROW * D_);
}

// ---------------------------------------------------------------------------
extern "C" void kernel_launch(void* const* d_in, const int* in_sizes, int n_in,
                              void* d_out, int out_size) {
    const float* x = (const float*)d_in[0];
    const float* w = (const float*)d_in[1];
    float* out = (float*)d_out;

    prepA_kernel<<<(NROW + KCB) / 8, 256>>>(x, w);
    prepW2_kernel<<<KCB / 256, 256>>>(w);
    vq_filter<<<NROW / BM, NT>>>();
    rescore_kernel<<<NROW / 8, 256>>>(x, w, out);
    finalize_kernel<<<1, 512>>>(out);
}

// round 11
// speedup vs baseline: 1.4504x; 1.3206x over previous
#include <cuda_runtime.h>
#include <stdint.h>

#define D_    64
#define NROW  16384
#define KCB   8192
#define BM    16
#define BN    128
#define NT    128
#define KT    (KCB / BN)     // 64
#define CAP   256
#define PI8   80             // int8 row pitch in smem (64 data + 16 pad)

__device__ float    g_xsq[NROW];
__device__ float    g_wsq[KCB];
__device__ float    g_xl1[NROW];
__device__ float    g_xamax[NROW];
__device__ int      g_wamax_bits;
__device__ int      g_wl1max_bits;
__device__ uint32_t g_xq8[NROW * 16];   // packed int8x4
__device__ uint32_t g_wq8[KCB * 16];
__device__ int      g_cnt[NROW];
__device__ int      g_cand[NROW * CAP];
__device__ float    g_rowloss[NROW];

// ---------------------------------------------------------------------------
__device__ __forceinline__ uint32_t smem_u32(const void* p) {
    uint32_t a;
    asm("{ .reg .u64 t; cvta.to.shared.u64 t, %1; cvt.u32.u64 %0, t; }" : "=r"(a) : "l"(p));
    return a;
}
__device__ __forceinline__ void cp16(uint32_t dst, const void* src) {
    asm volatile("cp.async.cg.shared.global [%0], [%1], 16;" :: "r"(dst), "l"(src));
}
__device__ __forceinline__ void cp_commit() { asm volatile("cp.async.commit_group;"); }
__device__ __forceinline__ void cp_wait1()  { asm volatile("cp.async.wait_group 1;"); }
__device__ __forceinline__ void cp_wait0()  { asm volatile("cp.async.wait_group 0;"); }

__device__ __forceinline__ int dp4a_(uint32_t a, uint32_t b, int c) {
    int d;
    asm("dp4a.s32.s32 %0, %1, %2, %3;" : "=r"(d) : "r"(a), "r"(b), "r"(c));
    return d;
}
__device__ __forceinline__ uint32_t pack4(float a, float b, float c, float d, float inv) {
    int q0 = __float2int_rn(a * inv) & 0xff;
    int q1 = __float2int_rn(b * inv) & 0xff;
    int q2 = __float2int_rn(c * inv) & 0xff;
    int q3 = __float2int_rn(d * inv) & 0xff;
    return (uint32_t)(q0 | (q1 << 8) | (q2 << 16) | (q3 << 24));
}

// ---------------------------------------------------------------------------
// prepA: warp-per-row. x rows: stats + int8 quantize + cnt reset.
//        w rows: stats + global atomicMax accumulators (idempotent).
// ---------------------------------------------------------------------------
__global__ __launch_bounds__(256) void prepA_kernel(const float* __restrict__ x,
                                                    const float* __restrict__ w) {
    int gw = (blockIdx.x * 256 + threadIdx.x) >> 5;
    int lane = threadIdx.x & 31;
    if (gw >= NROW + KCB) return;
    const bool isX = (gw < NROW);
    const float* src = isX ? x : w;
    int row = isX ? gw : gw - NROW;

    float2 v = ((const float2*)(src + (size_t)row * D_))[lane];
    float s  = v.x * v.x + v.y * v.y;
    float l1 = fabsf(v.x) + fabsf(v.y);
    float am = fmaxf(fabsf(v.x), fabsf(v.y));
#pragma unroll
    for (int o = 16; o > 0; o >>= 1) {
        s  += __shfl_xor_sync(0xffffffffu, s, o);
        l1 += __shfl_xor_sync(0xffffffffu, l1, o);
        am  = fmaxf(am, __shfl_xor_sync(0xffffffffu, am, o));
    }
    if (isX) {
        float amc = fmaxf(am, 1e-30f);
        float inv = 127.f / amc;
        int q0 = __float2int_rn(v.x * inv) & 0xff;
        int q1 = __float2int_rn(v.y * inv) & 0xff;
        uint32_t v16 = (uint32_t)(q0 | (q1 << 8));
        uint32_t hi = __shfl_down_sync(0xffffffffu, v16, 1);
        if (!(lane & 1)) g_xq8[row * 16 + (lane >> 1)] = v16 | (hi << 16);
        if (lane == 0) {
            g_xsq[row] = s; g_xl1[row] = l1; g_xamax[row] = amc; g_cnt[row] = 0;
        }
    } else if (lane == 0) {
        g_wsq[row] = s;
        atomicMax(&g_wamax_bits,  __float_as_int(am));
        atomicMax(&g_wl1max_bits, __float_as_int(l1));
    }
}

// ---------------------------------------------------------------------------
// prepW2: quantize w to int8 with global scale
// ---------------------------------------------------------------------------
__global__ __launch_bounds__(256) void prepW2_kernel(const float* __restrict__ w) {
    int r = blockIdx.x * 256 + threadIdx.x;
    if (r >= KCB) return;
    float wam = fmaxf(__int_as_float(g_wamax_bits), 1e-30f);
    float inv = 127.f / wam;
    const float4* wr = (const float4*)(w + (size_t)r * D_);
#pragma unroll
    for (int q = 0; q < 16; q++) {
        float4 v = wr[q];
        g_wq8[r * 16 + q] = pack4(v.x, v.y, v.z, v.w, inv);
    }
}

// ---------------------------------------------------------------------------
// vq_filter: int8 dp4a distance GEMM + provable candidate filter
// 16x128 tiles, 128 threads, TM=2 x TN=8; grid=1024 for SM load balance
// ---------------------------------------------------------------------------
__global__ __launch_bounds__(NT, 8) void vq_filter() {
    __shared__ uint8_t xsA[BM * PI8];            // 1280 B
    __shared__ uint8_t wsm[2][BN * PI8];         // 2 x 10240 B
    __shared__ float   wsqs[2][BN];              // 2 x 512 B

    const uint32_t sbA = smem_u32(xsA);
    const uint32_t sbW = smem_u32(wsm);
    const uint32_t sbQ = smem_u32(wsqs);

    const int t = threadIdx.x;
    const int tx = t & 15, ty = t >> 4;
    const int rowBase = blockIdx.x * BM;

    // A tile: 16 rows x 64B = 64 x 16B
    if (t < 64) {
        int r = t >> 2, q = t & 3;
        cp16(sbA + r * PI8 + q * 16, g_xq8 + (size_t)(rowBase + r) * 16 + q * 4);
    }
    auto issue = [&](int tt, int b) {
#pragma unroll
        for (int i = 0; i < 4; i++) {
            int idx = t + i * NT;                // 512 x 16B
            int r = idx >> 2, q = idx & 3;
            cp16(sbW + b * (BN * PI8) + r * PI8 + q * 16,
                 g_wq8 + ((size_t)tt * BN + r) * 16 + q * 4);
        }
        if (t < 32) cp16(sbQ + b * (BN * 4) + t * 16, g_wsq + tt * BN + t * 4);
    };

    issue(0, 0);
    cp_commit();

    // per-thread row state (rows ty + 8*r): margins computed from globals
    const float wam = fmaxf(__int_as_float(g_wamax_bits), 1e-30f);
    const float sw  = wam * (1.f / 127.f);
    const float l1w = __int_as_float(g_wl1max_bits);

    float xqs[2], gmin[2], m2B[2], c2s[2];
#pragma unroll
    for (int r = 0; r < 2; r++) {
        int row = rowBase + ty + 8 * r;
        float xam = g_xamax[row];
        float sx  = xam * (1.f / 127.f);
        float doterr = 0.5f * sw * g_xl1[row] + 0.5f * sx * l1w + 16.f * sx * sw;
        xqs[r]  = g_xsq[row];
        m2B[r]  = 4.f * doterr;
        c2s[r]  = -2.f * sx * sw;
        gmin[r] = 3.4e38f;
    }

    for (int tt = 0; tt < KT; tt++) {
        const int buf = tt & 1;
        if (tt + 1 < KT) { issue(tt + 1, buf ^ 1); cp_commit(); cp_wait1(); }
        else             { cp_wait0(); }
        __syncthreads();

        const uint8_t* wt = wsm[buf];
        int acc[2][8];
#pragma unroll
        for (int r = 0; r < 2; r++)
#pragma unroll
            for (int c = 0; c < 8; c++) acc[r][c] = 0;

#pragma unroll
        for (int kq2 = 0; kq2 < 8; kq2++) {      // 8 bytes of k per step
            uint2 a2[2], b2[8];
#pragma unroll
            for (int r = 0; r < 2; r++)
                a2[r] = *(const uint2*)(xsA + (ty + 8 * r) * PI8 + kq2 * 8);
#pragma unroll
            for (int c = 0; c < 8; c++)
                b2[c] = *(const uint2*)(wt + (tx + 16 * c) * PI8 + kq2 * 8);
#pragma unroll
            for (int r = 0; r < 2; r++)
#pragma unroll
                for (int c = 0; c < 8; c++) {
                    acc[r][c] = dp4a_(a2[r].x, b2[c].x, acc[r][c]);
                    acc[r][c] = dp4a_(a2[r].y, b2[c].y, acc[r][c]);
                }
        }

        // epilogue: stale-threshold superset window (thr fixed per tile)
        float thr[2];
#pragma unroll
        for (int r = 0; r < 2; r++) thr[r] = gmin[r] + m2B[r];

        const float* wqS = wsqs[buf];
#pragma unroll
        for (int c = 0; c < 8; c++) {
            int col = tx + 16 * c;
            float wq = wqS[col];
            int gcol = tt * BN + col;
#pragma unroll
            for (int r = 0; r < 2; r++) {
                float d = fmaf(c2s[r], (float)acc[r][c], xqs[r] + wq);
                if (d <= thr[r]) {
                    int row = rowBase + ty + 8 * r;
                    int p = atomicAdd(&g_cnt[row], 1);
                    if (p < CAP) g_cand[row * CAP + p] = gcol;
                }
                gmin[r] = fminf(gmin[r], d);
            }
        }
        // cross-lane tighten every 2nd tile (stale min only widens the window)
        if (tt & 1) {
#pragma unroll
            for (int r = 0; r < 2; r++) {
                float v = gmin[r];
                v = fminf(v, __shfl_xor_sync(0xffffffffu, v, 1));
                v = fminf(v, __shfl_xor_sync(0xffffffffu, v, 2));
                v = fminf(v, __shfl_xor_sync(0xffffffffu, v, 4));
                v = fminf(v, __shfl_xor_sync(0xffffffffu, v, 8));
                gmin[r] = v;
            }
        }
        __syncthreads();
    }
}

// ---------------------------------------------------------------------------
// rescore: warp-per-row exact fp32 argmin over candidates (R8-proven path)
// out: [0]=loss, [1..N*D]=quantized, [1+N*D..]=indices (float)
// ---------------------------------------------------------------------------
__global__ __launch_bounds__(256) void rescore_kernel(const float* __restrict__ x,
                                                      const float* __restrict__ w,
                                                      float* __restrict__ out) {
    int row = (blockIdx.x * 256 + threadIdx.x) >> 5;
    int lane = threadIdx.x & 31;
    if (row >= NROW) return;

    int cnt = g_cnt[row];
    if (cnt > CAP) cnt = CAP;
    const int* cl = g_cand + (size_t)row * CAP;
    float2 xv = ((const float2*)(x + (size_t)row * D_))[lane];

    int bc;
    if (cnt == 1) {
        bc = cl[0];
    } else {
        float xq = g_xsq[row];
        float bd = 3.4e38f;
        bc = 0x7fffffff;
        int i = 0;
        for (; i + 2 <= cnt; i += 2) {
            int c0 = cl[i], c1 = cl[i + 1];
            float2 w0 = ((const float2*)(w + (size_t)c0 * D_))[lane];
            float2 w1 = ((const float2*)(w + (size_t)c1 * D_))[lane];
            float p0 = xv.x * w0.x + xv.y * w0.y;
            float p1 = xv.x * w1.x + xv.y * w1.y;
#pragma unroll
            for (int o = 16; o > 0; o >>= 1) {
                p0 += __shfl_xor_sync(0xffffffffu, p0, o);
                p1 += __shfl_xor_sync(0xffffffffu, p1, o);
            }
            float d0 = xq + g_wsq[c0] - 2.f * p0;
            float d1 = xq + g_wsq[c1] - 2.f * p1;
            if (d0 < bd || (d0 == bd && c0 < bc)) { bd = d0; bc = c0; }
            if (d1 < bd || (d1 == bd && c1 < bc)) { bd = d1; bc = c1; }
        }
        if (i < cnt) {
            int c0 = cl[i];
            float2 w0 = ((const float2*)(w + (size_t)c0 * D_))[lane];
            float p0 = xv.x * w0.x + xv.y * w0.y;
#pragma unroll
            for (int o = 16; o > 0; o >>= 1) p0 += __shfl_xor_sync(0xffffffffu, p0, o);
            float d0 = xq + g_wsq[c0] - 2.f * p0;
            if (d0 < bd || (d0 == bd && c0 < bc)) { bd = d0; bc = c0; }
        }
    }

    float2 wv = ((const float2*)(w + (size_t)bc * D_))[lane];
    float* qo = out + 1 + (size_t)row * D_ + lane * 2;   // 4B-aligned: scalar stores
    qo[0] = wv.x;
    qo[1] = wv.y;
    if (lane == 0) out[1 + (size_t)NROW * D_ + row] = (float)bc;

    float dx = wv.x - xv.x, dy = wv.y - xv.y;
    float l = dx * dx + dy * dy;
#pragma unroll
    for (int o = 16; o > 0; o >>= 1) l += __shfl_xor_sync(0xffffffffu, l, o);
    if (lane == 0) g_rowloss[row] = l;
}

// ---------------------------------------------------------------------------
__global__ void finalize_kernel(float* __restrict__ out) {
    __shared__ float sm[512];
    float s = 0.f;
    for (int i = threadIdx.x; i < NROW; i += 512) s += g_rowloss[i];
    sm[threadIdx.x] = s;
    __syncthreads();
    for (int o = 256; o > 0; o >>= 1) {
        if (threadIdx.x < o) sm[threadIdx.x] += sm[threadIdx.x + o];
        __syncthreads();
    }
    if (threadIdx.x == 0) out[0] = 1.25f * sm[0] / (float)(NROW * D_);
}

// ---------------------------------------------------------------------------
extern "C" void kernel_launch(void* const* d_in, const int* in_sizes, int n_in,
                              void* d_out, int out_size) {
    const float* x = (const float*)d_in[0];
    const float* w = (const float*)d_in[1];
    float* out = (float*)d_out;

    prepA_kernel<<<(NROW + KCB) / 8, 256>>>(x, w);
    prepW2_kernel<<<KCB / 256, 256>>>(w);
    vq_filter<<<NROW / BM, NT>>>();
    rescore_kernel<<<NROW / 8, 256>>>(x, w, out);
    finalize_kernel<<<1, 512>>>(out);
}

// round 13
// speedup vs baseline: 2.1605x; 1.4896x over previous
#include <cuda_runtime.h>
#include <stdint.h>

#define D_    64
#define NROW  16384
#define KCB   8192
#define BM    16
#define BN    128
#define NT    128
#define KT    (KCB / BN)     // 64
#define CAPS  128            // per-row smem candidate cap
#define PI8   80             // int8 row pitch in smem (64 data + 16 pad)

__device__ float    g_xsq[NROW];
__device__ float    g_wsq[KCB];
__device__ float    g_xl1[NROW];
__device__ float    g_xamax[NROW];
__device__ int      g_wamax_bits;
__device__ int      g_wl1max_bits;
__device__ uint32_t g_xq8[NROW * 16];   // packed int8x4
__device__ uint32_t g_wq8[KCB * 16];
__device__ float    g_block_loss[NROW / BM];

// ---------------------------------------------------------------------------
__device__ __forceinline__ uint32_t smem_u32(const void* p) {
    uint32_t a;
    asm("{ .reg .u64 t; cvta.to.shared.u64 t, %1; cvt.u32.u64 %0, t; }" : "=r"(a) : "l"(p));
    return a;
}
__device__ __forceinline__ void cp16(uint32_t dst, const void* src) {
    asm volatile("cp.async.cg.shared.global [%0], [%1], 16;" :: "r"(dst), "l"(src));
}
__device__ __forceinline__ void cp_commit() { asm volatile("cp.async.commit_group;"); }
__device__ __forceinline__ void cp_wait1()  { asm volatile("cp.async.wait_group 1;"); }
__device__ __forceinline__ void cp_wait0()  { asm volatile("cp.async.wait_group 0;"); }

__device__ __forceinline__ int dp4a_(uint32_t a, uint32_t b, int c) {
    int d;
    asm("dp4a.s32.s32 %0, %1, %2, %3;" : "=r"(d) : "r"(a), "r"(b), "r"(c));
    return d;
}
__device__ __forceinline__ uint32_t pack4(float a, float b, float c, float d, float inv) {
    int q0 = __float2int_rn(a * inv) & 0xff;
    int q1 = __float2int_rn(b * inv) & 0xff;
    int q2 = __float2int_rn(c * inv) & 0xff;
    int q3 = __float2int_rn(d * inv) & 0xff;
    return (uint32_t)(q0 | (q1 << 8) | (q2 << 16) | (q3 << 24));
}

// ---------------------------------------------------------------------------
// prepA: warp-per-row. x rows: stats + int8 quantize. w rows: stats + maxes.
// ---------------------------------------------------------------------------
__global__ __launch_bounds__(256) void prepA_kernel(const float* __restrict__ x,
                                                    const float* __restrict__ w) {
    int gw = (blockIdx.x * 256 + threadIdx.x) >> 5;
    int lane = threadIdx.x & 31;
    if (gw >= NROW + KCB) return;
    const bool isX = (gw < NROW);
    const float* src = isX ? x : w;
    int row = isX ? gw : gw - NROW;

    float2 v = ((const float2*)(src + (size_t)row * D_))[lane];
    float s  = v.x * v.x + v.y * v.y;
    float l1 = fabsf(v.x) + fabsf(v.y);
    float am = fmaxf(fabsf(v.x), fabsf(v.y));
#pragma unroll
    for (int o = 16; o > 0; o >>= 1) {
        s  += __shfl_xor_sync(0xffffffffu, s, o);
        l1 += __shfl_xor_sync(0xffffffffu, l1, o);
        am  = fmaxf(am, __shfl_xor_sync(0xffffffffu, am, o));
    }
    if (isX) {
        float amc = fmaxf(am, 1e-30f);
        float inv = 127.f / amc;
        int q0 = __float2int_rn(v.x * inv) & 0xff;
        int q1 = __float2int_rn(v.y * inv) & 0xff;
        uint32_t v16 = (uint32_t)(q0 | (q1 << 8));
        uint32_t hi = __shfl_down_sync(0xffffffffu, v16, 1);
        if (!(lane & 1)) g_xq8[row * 16 + (lane >> 1)] = v16 | (hi << 16);
        if (lane == 0) {
            g_xsq[row] = s; g_xl1[row] = l1; g_xamax[row] = amc;
        }
    } else if (lane == 0) {
        g_wsq[row] = s;
        atomicMax(&g_wamax_bits,  __float_as_int(am));
        atomicMax(&g_wl1max_bits, __float_as_int(l1));
    }
}

// ---------------------------------------------------------------------------
// prepW2: quantize w to int8 with global scale
// ---------------------------------------------------------------------------
__global__ __launch_bounds__(256) void prepW2_kernel(const float* __restrict__ w) {
    int r = blockIdx.x * 256 + threadIdx.x;
    if (r >= KCB) return;
    float wam = fmaxf(__int_as_float(g_wamax_bits), 1e-30f);
    float inv = 127.f / wam;
    const float4* wr = (const float4*)(w + (size_t)r * D_);
#pragma unroll
    for (int q = 0; q < 16; q++) {
        float4 v = wr[q];
        g_wq8[r * 16 + q] = pack4(v.x, v.y, v.z, v.w, inv);
    }
}

// ---------------------------------------------------------------------------
// vq_fused: dp4a filter (smem candidates) + exact fp32 rescore + gather/loss
// 16x128 tiles, 128 threads, TM=2 x TN=8; grid=1024 for SM load balance
// out: [0]=loss, [1..N*D]=quantized, [1+N*D..]=indices (float)
// ---------------------------------------------------------------------------
__global__ __launch_bounds__(NT, 7) void vq_fused(const float* __restrict__ x,
                                                  const float* __restrict__ w,
                                                  float* __restrict__ out) {
    __shared__ uint8_t xsA[BM * PI8];            // 1280 B
    __shared__ uint8_t wsm[2][BN * PI8];         // 2 x 10240 B
    __shared__ float   wsqs[2][BN];              // 2 x 512 B
    __shared__ int     s_cnt[BM];
    __shared__ int     s_cand[BM][CAPS];         // 8192 B
    __shared__ int     s_idx[BM];
    __shared__ float   s_lred[NT / 32];

    const uint32_t sbA = smem_u32(xsA);
    const uint32_t sbW = smem_u32(wsm);
    const uint32_t sbQ = smem_u32(wsqs);

    const int t = threadIdx.x;
    const int tx = t & 15, ty = t >> 4;
    const int lane = t & 31, wid = t >> 5;
    const int rowBase = blockIdx.x * BM;

    if (t < BM) s_cnt[t] = 0;

    // A tile: 16 rows x 64B = 64 x 16B
    if (t < 64) {
        int r = t >> 2, q = t & 3;
        cp16(sbA + r * PI8 + q * 16, g_xq8 + (size_t)(rowBase + r) * 16 + q * 4);
    }
    auto issue = [&](int tt, int b) {
#pragma unroll
        for (int i = 0; i < 4; i++) {
            int idx = t + i * NT;                // 512 x 16B
            int r = idx >> 2, q = idx & 3;
            cp16(sbW + b * (BN * PI8) + r * PI8 + q * 16,
                 g_wq8 + ((size_t)tt * BN + r) * 16 + q * 4);
        }
        if (t < 32) cp16(sbQ + b * (BN * 4) + t * 16, g_wsq + tt * BN + t * 4);
    };

    issue(0, 0);
    cp_commit();

    // per-thread row state; margin = 4*doterr (E = 2*doterr on distances)
    const float wam = fmaxf(__int_as_float(g_wamax_bits), 1e-30f);
    const float sw  = wam * (1.f / 127.f);
    const float l1w = __int_as_float(g_wl1max_bits);

    float xqs[2], gmin[2], m2B[2], c2s[2];
#pragma unroll
    for (int r = 0; r < 2; r++) {
        int row = rowBase + ty + 8 * r;
        float xam = g_xamax[row];
        float sx  = xam * (1.f / 127.f);
        float doterr = 0.5f * sw * g_xl1[row] + 0.5f * sx * l1w + 16.f * sx * sw;
        xqs[r]  = g_xsq[row];
        m2B[r]  = 4.f * doterr;
        c2s[r]  = -2.f * sx * sw;
        gmin[r] = 3.4e38f;
    }

    for (int tt = 0; tt < KT; tt++) {
        const int buf = tt & 1;
        if (tt + 1 < KT) { issue(tt + 1, buf ^ 1); cp_commit(); cp_wait1(); }
        else             { cp_wait0(); }
        __syncthreads();

        const uint8_t* wt = wsm[buf];
        int acc[2][8];
#pragma unroll
        for (int r = 0; r < 2; r++)
#pragma unroll
            for (int c = 0; c < 8; c++) acc[r][c] = 0;

#pragma unroll
        for (int kq2 = 0; kq2 < 8; kq2++) {      // 8 bytes of k per step
            uint2 a2[2], b2[8];
#pragma unroll
            for (int r = 0; r < 2; r++)
                a2[r] = *(const uint2*)(xsA + (ty + 8 * r) * PI8 + kq2 * 8);
#pragma unroll
            for (int c = 0; c < 8; c++)
                b2[c] = *(const uint2*)(wt + (tx + 16 * c) * PI8 + kq2 * 8);
#pragma unroll
            for (int r = 0; r < 2; r++)
#pragma unroll
                for (int c = 0; c < 8; c++) {
                    acc[r][c] = dp4a_(a2[r].x, b2[c].x, acc[r][c]);
                    acc[r][c] = dp4a_(a2[r].y, b2[c].y, acc[r][c]);
                }
        }

        // ---- epilogue: compute all distances first ----
        const float* wqS = wsqs[buf];
        float dbuf[2][8];
#pragma unroll
        for (int c = 0; c < 8; c++) {
            float wq = wqS[tx + 16 * c];
#pragma unroll
            for (int r = 0; r < 2; r++) {
                float d = fmaf(c2s[r], (float)acc[r][c], xqs[r] + wq);
                dbuf[r][c] = d;
                gmin[r] = fminf(gmin[r], d);
            }
        }
        // tighten across the 16 lanes of this row (this tile included)
#pragma unroll
        for (int r = 0; r < 2; r++) {
            float v = gmin[r];
            v = fminf(v, __shfl_xor_sync(0xffffffffu, v, 1));
            v = fminf(v, __shfl_xor_sync(0xffffffffu, v, 2));
            v = fminf(v, __shfl_xor_sync(0xffffffffu, v, 4));
            v = fminf(v, __shfl_xor_sync(0xffffffffu, v, 8));
            gmin[r] = v;
        }
        // append with post-tile threshold (superset: final gmin <= current)
#pragma unroll
        for (int c = 0; c < 8; c++) {
            int gcol = tt * BN + tx + 16 * c;
#pragma unroll
            for (int r = 0; r < 2; r++) {
                if (dbuf[r][c] <= gmin[r] + m2B[r]) {
                    int lrow = ty + 8 * r;
                    int p = atomicAdd(&s_cnt[lrow], 1);
                    if (p < CAPS) s_cand[lrow][p] = gcol;
                }
            }
        }
        __syncthreads();
    }

    // ---- in-CTA exact fp32 rescore: warp wid handles rows 4*wid..4*wid+3 ----
#pragma unroll 1
    for (int rr = 0; rr < 4; rr++) {
        int lrow = wid * 4 + rr;
        int row = rowBase + lrow;
        int cnt = s_cnt[lrow];
        if (cnt > CAPS) cnt = CAPS;
        float2 xv = ((const float2*)(x + (size_t)row * D_))[lane];
        float xq = g_xsq[row];
        float bd = 3.4e38f;
        int   bc = 0x7fffffff;
        for (int i = 0; i < cnt; i++) {
            int c0 = s_cand[lrow][i];
            float2 w0 = ((const float2*)(w + (size_t)c0 * D_))[lane];
            float p0 = xv.x * w0.x + xv.y * w0.y;
#pragma unroll
            for (int o = 16; o > 0; o >>= 1) p0 += __shfl_xor_sync(0xffffffffu, p0, o);
            float d0 = xq + g_wsq[c0] - 2.f * p0;
            if (d0 < bd || (d0 == bd && c0 < bc)) { bd = d0; bc = c0; }
        }
        if (lane == 0) {
            s_idx[lrow] = bc;
            out[1 + (size_t)NROW * D_ + row] = (float)bc;
        }
    }
    __syncthreads();

    // ---- quantized gather + deterministic loss partial ----
    float lsum = 0.f;
#pragma unroll
    for (int i = 0; i < 8; i++) {
        int idx = t + i * NT;                 // 1024 elements
        int r = idx >> 6, dc = idx & 63;
        float q = w[(size_t)s_idx[r] * D_ + dc];
        out[1 + (size_t)(rowBase + r) * D_ + dc] = q;
        float xf = x[(size_t)(rowBase + r) * D_ + dc];
        float df = q - xf;
        lsum += df * df;
    }
#pragma unroll
    for (int o = 16; o > 0; o >>= 1) lsum += __shfl_down_sync(0xffffffffu, lsum, o);
    if (lane == 0) s_lred[wid] = lsum;
    __syncthreads();
    if (t == 0) {
        float s = 0.f;
#pragma unroll
        for (int wI = 0; wI < NT / 32; wI++) s += s_lred[wI];
        g_block_loss[blockIdx.x] = s;
    }
}

// ---------------------------------------------------------------------------
__global__ void finalize_kernel(float* __restrict__ out) {
    __shared__ float sm[512];
    float s = 0.f;
    for (int i = threadIdx.x; i < NROW / BM; i += 512) s += g_block_loss[i];
    sm[threadIdx.x] = s;
    __syncthreads();
    for (int o = 256; o > 0; o >>= 1) {
        if (threadIdx.x < o) sm[threadIdx.x] += sm[threadIdx.x + o];
        __syncthreads();
    }
    if (threadIdx.x == 0) out[0] = 1.25f * sm[0] / (float)(NROW * D_);
}

// ---------------------------------------------------------------------------
extern "C" void kernel_launch(void* const* d_in, const int* in_sizes, int n_in,
                              void* d_out, int out_size) {
    const float* x = (const float*)d_in[0];
    const float* w = (const float*)d_in[1];
    float* out = (float*)d_out;

    prepA_kernel<<<(NROW + KCB) / 8, 256>>>(x, w);
    prepW2_kernel<<<KCB / 256, 256>>>(w);
    vq_fused<<<NROW / BM, NT>>>(x, w, out);
    finalize_kernel<<<1, 512>>>(out);
}